// round 7
// baseline (speedup 1.0000x reference)
#include <cuda_runtime.h>
#include <math.h>
#include <stdint.h>

// Problem constants
#define D_DIM 1024
#define S_LEN 2048
#define NB    2
#define NH    16
#define HD    64
#define NTOK  4096            // B*S
// -ln(10000)*2/64
#define NEG_LOG_BASE_OVER_32 (-0.28782313662425572f)

// ---------------- device scratch (allocation-free rule) ----------------------
__device__ float g_xn[NTOK * D_DIM];                 // layernorm(x)
__device__ float g_q[NB * NH * S_LEN * HD];          // [b,h,s,hd]
__device__ float g_k[NB * NH * S_LEN * HD];
__device__ float g_v[NB * NH * S_LEN * HD];
__device__ float g_attn[NTOK * D_DIM];               // [b,s,h,hd] token-major

// ---------------- tf32 helpers ----------------------------------------------
__device__ __forceinline__ uint32_t f2tf(float f) {
    uint32_t u;
    asm("cvt.rna.tf32.f32 %0, %1;" : "=r"(u) : "f"(f));
    return u;
}

// D = A(m16k8, row) * B(k8n8, col) + C, tf32 inputs, f32 accum
__device__ __forceinline__ void mma_tf32(float d[4], const uint32_t a[4],
                                         const uint32_t b[2], const float c[4]) {
    asm volatile(
        "mma.sync.aligned.m16n8k8.row.col.f32.tf32.tf32.f32 "
        "{%0,%1,%2,%3}, {%4,%5,%6,%7}, {%8,%9}, {%10,%11,%12,%13};"
        : "=f"(d[0]), "=f"(d[1]), "=f"(d[2]), "=f"(d[3])
        : "r"(a[0]), "r"(a[1]), "r"(a[2]), "r"(a[3]),
          "r"(b[0]), "r"(b[1]),
          "f"(c[0]), "f"(c[1]), "f"(c[2]), "f"(c[3]));
}

// ======================= 1) LayerNorm over D=1024 ============================
// One row per 256-thread block; one float4 per thread.
__global__ __launch_bounds__(256) void ln_kernel(const float* __restrict__ x,
                                                 const float* __restrict__ scale,
                                                 const float* __restrict__ bias) {
    int t = threadIdx.x;
    const float4* xr = (const float4*)(x + (size_t)blockIdx.x * D_DIM);
    float4 v = xr[t];
    float s  = v.x + v.y + v.z + v.w;
    float ss = v.x * v.x + v.y * v.y + v.z * v.z + v.w * v.w;
#pragma unroll
    for (int off = 16; off; off >>= 1) {
        s  += __shfl_xor_sync(0xffffffffu, s,  off);
        ss += __shfl_xor_sync(0xffffffffu, ss, off);
    }
    __shared__ float sm[8], sm2[8];
    int w = t >> 5;
    if ((t & 31) == 0) { sm[w] = s; sm2[w] = ss; }
    __syncthreads();
    if (t < 32) {
        float a = (t < 8) ? sm[t]  : 0.f;
        float b = (t < 8) ? sm2[t] : 0.f;
#pragma unroll
        for (int off = 4; off; off >>= 1) {
            a += __shfl_xor_sync(0xffffffffu, a, off);
            b += __shfl_xor_sync(0xffffffffu, b, off);
        }
        if (t == 0) { sm[0] = a; sm2[0] = b; }
    }
    __syncthreads();
    float mu   = sm[0]  * (1.f / 1024.f);
    float var  = sm2[0] * (1.f / 1024.f) - mu * mu;
    float rstd = rsqrtf(var + 1e-6f);
    float4 sc = ((const float4*)scale)[t];
    float4 bi = ((const float4*)bias)[t];
    float4 o;
    o.x = (v.x - mu) * rstd * sc.x + bi.x;
    o.y = (v.y - mu) * rstd * sc.y + bi.y;
    o.z = (v.z - mu) * rstd * sc.z + bi.z;
    o.w = (v.w - mu) * rstd * sc.w + bi.w;
    ((float4*)(g_xn + (size_t)blockIdx.x * D_DIM))[t] = o;
}

// ======================= 2)/5) tf32 tensor-core GEMM =========================
// 128x128 block tile, K-block 32, 8 warps (2x4), warp tile 64x32.
#define GST 136
__device__ __forceinline__ int asw(int k, int m) { return k * GST + (m ^ (((k >> 2) & 7) << 2)); }

__global__ __launch_bounds__(256, 2) void gemm_tc(const float* __restrict__ Bmat,
                                                  const float* __restrict__ bias,
                                                  float* __restrict__ outC,
                                                  int mode, int N) {
    __shared__ uint32_t As[32 * GST];
    __shared__ uint32_t Bs[32 * GST];
    const float* A = mode ? g_attn : g_xn;
    const int K = 1024;
    int tid = threadIdx.x;
    int lane = tid & 31, warp = tid >> 5;
    int wm = warp >> 2, wn = warp & 3;
    int g = lane >> 2, tq = lane & 3;
    int row0 = blockIdx.y * 128, col0 = blockIdx.x * 128;

    float acc[4][4][4];
#pragma unroll
    for (int i = 0; i < 4; i++)
#pragma unroll
        for (int j = 0; j < 4; j++)
#pragma unroll
            for (int r = 0; r < 4; r++) acc[i][j][r] = 0.f;

    for (int kb = 0; kb < K / 32; kb++) {
        int k0 = kb * 32;
#pragma unroll
        for (int p = 0; p < 4; p++) {            // A: 128 rows x 32 k, transposed+swizzled
            int idx = tid + p * 256;
            int r = idx >> 3, c4 = (idx & 7) * 4;
            float4 f = *(const float4*)(A + (size_t)(row0 + r) * K + k0 + c4);
            As[asw(c4 + 0, r)] = f2tf(f.x);
            As[asw(c4 + 1, r)] = f2tf(f.y);
            As[asw(c4 + 2, r)] = f2tf(f.z);
            As[asw(c4 + 3, r)] = f2tf(f.w);
        }
#pragma unroll
        for (int p = 0; p < 4; p++) {            // B: 32 k x 128 n
            int idx = tid + p * 256;
            int r = idx >> 5, c4 = (idx & 31) * 4;
            float4 f = *(const float4*)(Bmat + (size_t)(k0 + r) * N + col0 + c4);
            uint4 u;
            u.x = f2tf(f.x); u.y = f2tf(f.y); u.z = f2tf(f.z); u.w = f2tf(f.w);
            *(uint4*)&Bs[r * GST + c4] = u;
        }
        __syncthreads();
#pragma unroll
        for (int ks = 0; ks < 4; ks++) {
            int kk = ks * 8;
            uint32_t a[4][4], b[4][2];
#pragma unroll
            for (int i = 0; i < 4; i++) {
                int m = wm * 64 + i * 16 + g;
                a[i][0] = As[asw(kk + tq,     m)];
                a[i][1] = As[asw(kk + tq,     m + 8)];
                a[i][2] = As[asw(kk + tq + 4, m)];
                a[i][3] = As[asw(kk + tq + 4, m + 8)];
            }
#pragma unroll
            for (int j = 0; j < 4; j++) {
                int n = wn * 32 + j * 8 + g;
                b[j][0] = Bs[(kk + tq) * GST + n];
                b[j][1] = Bs[(kk + tq + 4) * GST + n];
            }
#pragma unroll
            for (int i = 0; i < 4; i++)
#pragma unroll
                for (int j = 0; j < 4; j++) mma_tf32(acc[i][j], a[i], b[j], acc[i][j]);
        }
        __syncthreads();
    }

#pragma unroll
    for (int i = 0; i < 4; i++) {
        int rbase = row0 + wm * 64 + i * 16 + g;
#pragma unroll
        for (int j = 0; j < 4; j++) {
            int cbase = col0 + wn * 32 + j * 8 + 2 * tq;
#pragma unroll
            for (int h = 0; h < 2; h++) {
                int row = rbase + 8 * h;
                float2 f;
                f.x = acc[i][j][2 * h + 0] + bias[cbase + 0];
                f.y = acc[i][j][2 * h + 1] + bias[cbase + 1];
                if (mode) {
                    *(float2*)(outC + (size_t)row * N + cbase) = f;
                } else {
                    int part = cbase >> 10;
                    float* dst = (part == 0) ? g_q : (part == 1) ? g_k : g_v;
                    int wd = cbase & 1023;
                    int head = wd >> 6, hd = wd & 63;
                    int b = row >> 11, s = row & 2047;
                    size_t di = ((((size_t)b * NH + head) * S_LEN) + s) * HD + hd;
                    *(float2*)(dst + di) = f;
                }
            }
        }
    }
}

// ================= 3) per-head LayerNorm + RoPE, q & k share sincos =========
__global__ __launch_bounds__(256) void lnrope_kernel(const float* __restrict__ q_scale,
                                                     const float* __restrict__ k_scale) {
    int gw   = (blockIdx.x * 256 + threadIdx.x) >> 5;   // 0..65535 = (b*H+h)*S + s
    int lane = threadIdx.x & 31;
    int s = gw & 2047;

    float inv = expf((float)lane * NEG_LOG_BASE_OVER_32);
    float ang = (float)s * inv;
    float c, sn;
    sincosf(ang, &sn, &c);

#pragma unroll
    for (int sel = 0; sel < 2; sel++) {
        float* p = (sel ? g_k : g_q) + (size_t)gw * 64;
        const float* sc = sel ? k_scale : q_scale;
        float x0 = p[lane], x1 = p[lane + 32];
        float sum = x0 + x1;
#pragma unroll
        for (int off = 16; off; off >>= 1) sum += __shfl_xor_sync(0xffffffffu, sum, off);
        float mu = sum * (1.f / 64.f);
        float d0 = x0 - mu, d1 = x1 - mu;
        float vs = d0 * d0 + d1 * d1;
#pragma unroll
        for (int off = 16; off; off >>= 1) vs += __shfl_xor_sync(0xffffffffu, vs, off);
        float rstd = rsqrtf(vs * (1.f / 64.f) + 1e-6f);
        float y0 = d0 * rstd * sc[lane];
        float y1 = d1 * rstd * sc[lane + 32];
        p[lane]      = y0 * c - y1 * sn;
        p[lane + 32] = y1 * c + y0 * sn;
    }
}

// ======================= 4) flash attention, tf32 MMA ========================
// CTA = 64 queries, 4 warps (warp = 16 q x 64 keys). Q lives in registers.
// Smem: KPs[64][68] (K tile, reused as P), Vs[64][68]  -> ~34.8KB static.
// __launch_bounds__(128,3): 3 CTAs/SM (12 warps) for latency hiding.
#define AST 68

__global__ __launch_bounds__(128, 3) void attn_tc() {
    __shared__ uint32_t KPs[64 * AST];
    __shared__ uint32_t Vs[64 * AST];

    int tid = threadIdx.x, lane = tid & 31, w = tid >> 5;
    int g = lane >> 2, tq = lane & 3;
    int bh = blockIdx.y, qt = blockIdx.x;                // qt: 32 tiles of 64 q
    const float* kb = g_k + (size_t)bh * S_LEN * HD;
    const float* vb = g_v + (size_t)bh * S_LEN * HD;

    // ---- Q fragments in registers (reused across all 32 key tiles) ----
    uint32_t qa[8][4];
    {
        const float* q0 = g_q + ((size_t)bh * S_LEN + qt * 64 + w * 16 + g) * HD;
        const float* q1 = q0 + 8 * HD;
#pragma unroll
        for (int ks = 0; ks < 8; ks++) {
            qa[ks][0] = f2tf(q0[8 * ks + tq]     * 0.125f);
            qa[ks][1] = f2tf(q1[8 * ks + tq]     * 0.125f);
            qa[ks][2] = f2tf(q0[8 * ks + tq + 4] * 0.125f);
            qa[ks][3] = f2tf(q1[8 * ks + tq + 4] * 0.125f);
        }
    }

    float o[8][4], mr[2], lr[2];
    mr[0] = mr[1] = -1e30f;
    lr[0] = lr[1] = 0.f;
#pragma unroll
    for (int j = 0; j < 8; j++)
#pragma unroll
        for (int r = 0; r < 4; r++) o[j][r] = 0.f;

    for (int kt = 0; kt < S_LEN / 64; kt++) {
        __syncthreads();                                 // prev-iter reads done
        const float* kbt = kb + kt * 64 * 64;
        const float* vbt = vb + kt * 64 * 64;
#pragma unroll
        for (int p = 0; p < 8; p++) {                    // stage K,V (64x64 each)
            int idx = tid + p * 128;
            int r = idx >> 4, c4 = (idx & 15) * 4;
            float4 fk = *(const float4*)(kbt + r * 64 + c4);
            uint4 uk;
            uk.x = f2tf(fk.x); uk.y = f2tf(fk.y); uk.z = f2tf(fk.z); uk.w = f2tf(fk.w);
            *(uint4*)&KPs[r * AST + c4] = uk;
            float4 fv = *(const float4*)(vbt + r * 64 + c4);
            uint4 uv;
            uv.x = f2tf(fv.x); uv.y = f2tf(fv.y); uv.z = f2tf(fv.z); uv.w = f2tf(fv.w);
            *(uint4*)&Vs[r * AST + c4] = uv;
        }
        __syncthreads();

        // ---- S = Q @ K^T ----
        float s[8][4];
#pragma unroll
        for (int j = 0; j < 8; j++)
#pragma unroll
            for (int r = 0; r < 4; r++) s[j][r] = 0.f;
#pragma unroll
        for (int ks = 0; ks < 8; ks++) {
            int kk = ks * 8;
            uint32_t b[8][2];
#pragma unroll
            for (int j = 0; j < 8; j++) {
                int n = j * 8 + g;
                b[j][0] = KPs[n * AST + kk + tq];
                b[j][1] = KPs[n * AST + kk + tq + 4];
            }
#pragma unroll
            for (int j = 0; j < 8; j++) mma_tf32(s[j], qa[ks], b[j], s[j]);
        }
        __syncthreads();                                 // K reads done before P overlay

        // ---- online softmax; write P into KPs (row = CTA-local q) ----
#pragma unroll
        for (int h = 0; h < 2; h++) {
            float rm = -1e30f;
#pragma unroll
            for (int j = 0; j < 8; j++)
                rm = fmaxf(rm, fmaxf(s[j][2 * h], s[j][2 * h + 1]));
            rm = fmaxf(rm, __shfl_xor_sync(0xffffffffu, rm, 1));
            rm = fmaxf(rm, __shfl_xor_sync(0xffffffffu, rm, 2));
            float mn = fmaxf(mr[h], rm);
            float alpha = __expf(mr[h] - mn);
            mr[h] = mn;
            int row = w * 16 + h * 8 + g;
            float rs = 0.f;
#pragma unroll
            for (int j = 0; j < 8; j++) {
                float p0 = __expf(s[j][2 * h] - mn);
                float p1 = __expf(s[j][2 * h + 1] - mn);
                rs += p0 + p1;
                uint2 u; u.x = f2tf(p0); u.y = f2tf(p1);
                *(uint2*)&KPs[row * AST + j * 8 + 2 * tq] = u;
            }
            rs += __shfl_xor_sync(0xffffffffu, rs, 1);
            rs += __shfl_xor_sync(0xffffffffu, rs, 2);
            lr[h] = lr[h] * alpha + rs;
#pragma unroll
            for (int j = 0; j < 8; j++) {
                o[j][2 * h]     *= alpha;
                o[j][2 * h + 1] *= alpha;
            }
        }
        __syncwarp();                                    // P visible within warp

        // ---- O += P @ V  (warp reads only its own 16 P rows) ----
#pragma unroll
        for (int ks = 0; ks < 8; ks++) {
            int kk = ks * 8;
            uint32_t a[4], b[8][2];
            int m = w * 16 + g;
            a[0] = KPs[m * AST + kk + tq];
            a[1] = KPs[(m + 8) * AST + kk + tq];
            a[2] = KPs[m * AST + kk + tq + 4];
            a[3] = KPs[(m + 8) * AST + kk + tq + 4];
#pragma unroll
            for (int j = 0; j < 8; j++) {
                int n = j * 8 + g;
                b[j][0] = Vs[(kk + tq) * AST + n];
                b[j][1] = Vs[(kk + tq + 4) * AST + n];
            }
#pragma unroll
            for (int j = 0; j < 8; j++) mma_tf32(o[j], a, b[j], o[j]);
        }
    }

    // ---- epilogue: divide by l, scatter token-major [b,s,h,hd] ----
    int b = bh >> 4, h4 = bh & 15;
#pragma unroll
    for (int h = 0; h < 2; h++) {
        float invl = 1.f / lr[h];
        int srow = qt * 64 + w * 16 + h * 8 + g;
#pragma unroll
        for (int j = 0; j < 8; j++) {
            float2 f;
            f.x = o[j][2 * h]     * invl;
            f.y = o[j][2 * h + 1] * invl;
            int col = j * 8 + 2 * tq;
            *(float2*)(g_attn + (((size_t)b * S_LEN + srow) * NH + h4) * HD + col) = f;
        }
    }
}

// =========================== launch ==========================================
extern "C" void kernel_launch(void* const* d_in, const int* in_sizes, int n_in,
                              void* d_out, int out_size) {
    const float* x        = (const float*)d_in[0];
    const float* w_qkv    = (const float*)d_in[1];
    const float* b_qkv    = (const float*)d_in[2];
    const float* w_out    = (const float*)d_in[3];
    const float* b_out    = (const float*)d_in[4];
    const float* ln_scale = (const float*)d_in[5];
    const float* ln_bias  = (const float*)d_in[6];
    const float* q_scale  = (const float*)d_in[7];
    const float* k_scale  = (const float*)d_in[8];
    float* out = (float*)d_out;

    ln_kernel<<<NTOK, 256>>>(x, ln_scale, ln_bias);
    gemm_tc<<<dim3(3 * D_DIM / 128, NTOK / 128), 256>>>(w_qkv, b_qkv, nullptr, 0, 3 * D_DIM);
    lnrope_kernel<<<NB * NH * S_LEN / 8, 256>>>(q_scale, k_scale);
    attn_tc<<<dim3(S_LEN / 64, NB * NH), 128>>>();
    gemm_tc<<<dim3(D_DIM / 128, NTOK / 128), 256>>>(w_out, b_out, out, 1, D_DIM);
}

// round 8
// speedup vs baseline: 1.1106x; 1.1106x over previous
#include <cuda_runtime.h>
#include <math.h>
#include <stdint.h>

// Problem constants
#define D_DIM 1024
#define S_LEN 2048
#define NB    2
#define NH    16
#define HD    64
#define NTOK  4096            // B*S
// -ln(10000)*2/64
#define NEG_LOG_BASE_OVER_32 (-0.28782313662425572f)

// ---------------- device scratch (allocation-free rule) ----------------------
__device__ float g_xn[NTOK * D_DIM];                 // layernorm(x)
__device__ float g_q[NB * NH * S_LEN * HD];          // [b,h,s,hd]
__device__ float g_k[NB * NH * S_LEN * HD];
__device__ float g_v[NB * NH * S_LEN * HD];
__device__ float g_attn[NTOK * D_DIM];               // [b,s,h,hd] token-major

// ---------------- tf32 helpers ----------------------------------------------
__device__ __forceinline__ uint32_t f2tf(float f) {
    uint32_t u;
    asm("cvt.rna.tf32.f32 %0, %1;" : "=r"(u) : "f"(f));
    return u;
}

// D = A(m16k8, row) * B(k8n8, col) + C, tf32 inputs, f32 accum
__device__ __forceinline__ void mma_tf32(float d[4], const uint32_t a[4],
                                         const uint32_t b[2], const float c[4]) {
    asm volatile(
        "mma.sync.aligned.m16n8k8.row.col.f32.tf32.tf32.f32 "
        "{%0,%1,%2,%3}, {%4,%5,%6,%7}, {%8,%9}, {%10,%11,%12,%13};"
        : "=f"(d[0]), "=f"(d[1]), "=f"(d[2]), "=f"(d[3])
        : "r"(a[0]), "r"(a[1]), "r"(a[2]), "r"(a[3]),
          "r"(b[0]), "r"(b[1]),
          "f"(c[0]), "f"(c[1]), "f"(c[2]), "f"(c[3]));
}

#define CP_COMMIT() asm volatile("cp.async.commit_group;" ::: "memory")
#define CP_WAIT(N)  asm volatile("cp.async.wait_group %0;" :: "n"(N) : "memory")

// ======================= 1) LayerNorm over D=1024 ============================
__global__ __launch_bounds__(256) void ln_kernel(const float* __restrict__ x,
                                                 const float* __restrict__ scale,
                                                 const float* __restrict__ bias) {
    int t = threadIdx.x;
    const float4* xr = (const float4*)(x + (size_t)blockIdx.x * D_DIM);
    float4 v = xr[t];
    float s  = v.x + v.y + v.z + v.w;
    float ss = v.x * v.x + v.y * v.y + v.z * v.z + v.w * v.w;
#pragma unroll
    for (int off = 16; off; off >>= 1) {
        s  += __shfl_xor_sync(0xffffffffu, s,  off);
        ss += __shfl_xor_sync(0xffffffffu, ss, off);
    }
    __shared__ float sm[8], sm2[8];
    int w = t >> 5;
    if ((t & 31) == 0) { sm[w] = s; sm2[w] = ss; }
    __syncthreads();
    if (t < 32) {
        float a = (t < 8) ? sm[t]  : 0.f;
        float b = (t < 8) ? sm2[t] : 0.f;
#pragma unroll
        for (int off = 4; off; off >>= 1) {
            a += __shfl_xor_sync(0xffffffffu, a, off);
            b += __shfl_xor_sync(0xffffffffu, b, off);
        }
        if (t == 0) { sm[0] = a; sm2[0] = b; }
    }
    __syncthreads();
    float mu   = sm[0]  * (1.f / 1024.f);
    float var  = sm2[0] * (1.f / 1024.f) - mu * mu;
    float rstd = rsqrtf(var + 1e-6f);
    float4 sc = ((const float4*)scale)[t];
    float4 bi = ((const float4*)bias)[t];
    float4 o;
    o.x = (v.x - mu) * rstd * sc.x + bi.x;
    o.y = (v.y - mu) * rstd * sc.y + bi.y;
    o.z = (v.z - mu) * rstd * sc.z + bi.z;
    o.w = (v.w - mu) * rstd * sc.w + bi.w;
    ((float4*)(g_xn + (size_t)blockIdx.x * D_DIM))[t] = o;
}

// ======================= 2)/5) tf32 tensor-core GEMM =========================
#define GST 136
__device__ __forceinline__ int asw(int k, int m) { return k * GST + (m ^ (((k >> 2) & 7) << 2)); }

__global__ __launch_bounds__(256, 2) void gemm_tc(const float* __restrict__ Bmat,
                                                  const float* __restrict__ bias,
                                                  float* __restrict__ outC,
                                                  int mode, int N) {
    __shared__ uint32_t As[32 * GST];
    __shared__ uint32_t Bs[32 * GST];
    const float* A = mode ? g_attn : g_xn;
    const int K = 1024;
    int tid = threadIdx.x;
    int lane = tid & 31, warp = tid >> 5;
    int wm = warp >> 2, wn = warp & 3;
    int g = lane >> 2, tq = lane & 3;
    int row0 = blockIdx.y * 128, col0 = blockIdx.x * 128;

    float acc[4][4][4];
#pragma unroll
    for (int i = 0; i < 4; i++)
#pragma unroll
        for (int j = 0; j < 4; j++)
#pragma unroll
            for (int r = 0; r < 4; r++) acc[i][j][r] = 0.f;

    for (int kb = 0; kb < K / 32; kb++) {
        int k0 = kb * 32;
#pragma unroll
        for (int p = 0; p < 4; p++) {            // A: 128 rows x 32 k, transposed+swizzled
            int idx = tid + p * 256;
            int r = idx >> 3, c4 = (idx & 7) * 4;
            float4 f = *(const float4*)(A + (size_t)(row0 + r) * K + k0 + c4);
            As[asw(c4 + 0, r)] = f2tf(f.x);
            As[asw(c4 + 1, r)] = f2tf(f.y);
            As[asw(c4 + 2, r)] = f2tf(f.z);
            As[asw(c4 + 3, r)] = f2tf(f.w);
        }
#pragma unroll
        for (int p = 0; p < 4; p++) {            // B: 32 k x 128 n
            int idx = tid + p * 256;
            int r = idx >> 5, c4 = (idx & 31) * 4;
            float4 f = *(const float4*)(Bmat + (size_t)(k0 + r) * N + col0 + c4);
            uint4 u;
            u.x = f2tf(f.x); u.y = f2tf(f.y); u.z = f2tf(f.z); u.w = f2tf(f.w);
            *(uint4*)&Bs[r * GST + c4] = u;
        }
        __syncthreads();
#pragma unroll
        for (int ks = 0; ks < 4; ks++) {
            int kk = ks * 8;
            uint32_t a[4][4], b[4][2];
#pragma unroll
            for (int i = 0; i < 4; i++) {
                int m = wm * 64 + i * 16 + g;
                a[i][0] = As[asw(kk + tq,     m)];
                a[i][1] = As[asw(kk + tq,     m + 8)];
                a[i][2] = As[asw(kk + tq + 4, m)];
                a[i][3] = As[asw(kk + tq + 4, m + 8)];
            }
#pragma unroll
            for (int j = 0; j < 4; j++) {
                int n = wn * 32 + j * 8 + g;
                b[j][0] = Bs[(kk + tq) * GST + n];
                b[j][1] = Bs[(kk + tq + 4) * GST + n];
            }
#pragma unroll
            for (int i = 0; i < 4; i++)
#pragma unroll
                for (int j = 0; j < 4; j++) mma_tf32(acc[i][j], a[i], b[j], acc[i][j]);
        }
        __syncthreads();
    }

#pragma unroll
    for (int i = 0; i < 4; i++) {
        int rbase = row0 + wm * 64 + i * 16 + g;
#pragma unroll
        for (int j = 0; j < 4; j++) {
            int cbase = col0 + wn * 32 + j * 8 + 2 * tq;
#pragma unroll
            for (int h = 0; h < 2; h++) {
                int row = rbase + 8 * h;
                float2 f;
                f.x = acc[i][j][2 * h + 0] + bias[cbase + 0];
                f.y = acc[i][j][2 * h + 1] + bias[cbase + 1];
                if (mode) {
                    *(float2*)(outC + (size_t)row * N + cbase) = f;
                } else {
                    int part = cbase >> 10;
                    float* dst = (part == 0) ? g_q : (part == 1) ? g_k : g_v;
                    int wd = cbase & 1023;
                    int head = wd >> 6, hd = wd & 63;
                    int b = row >> 11, s = row & 2047;
                    size_t di = ((((size_t)b * NH + head) * S_LEN) + s) * HD + hd;
                    *(float2*)(dst + di) = f;
                }
            }
        }
    }
}

// ================= 3) per-head LayerNorm + RoPE, q & k share sincos =========
__global__ __launch_bounds__(256) void lnrope_kernel(const float* __restrict__ q_scale,
                                                     const float* __restrict__ k_scale) {
    int gw   = (blockIdx.x * 256 + threadIdx.x) >> 5;   // (b*H+h)*S + s
    int lane = threadIdx.x & 31;
    int s = gw & 2047;

    float inv = expf((float)lane * NEG_LOG_BASE_OVER_32);
    float ang = (float)s * inv;
    float c, sn;
    sincosf(ang, &sn, &c);

#pragma unroll
    for (int sel = 0; sel < 2; sel++) {
        float* p = (sel ? g_k : g_q) + (size_t)gw * 64;
        const float* sc = sel ? k_scale : q_scale;
        float x0 = p[lane], x1 = p[lane + 32];
        float sum = x0 + x1;
#pragma unroll
        for (int off = 16; off; off >>= 1) sum += __shfl_xor_sync(0xffffffffu, sum, off);
        float mu = sum * (1.f / 64.f);
        float d0 = x0 - mu, d1 = x1 - mu;
        float vs = d0 * d0 + d1 * d1;
#pragma unroll
        for (int off = 16; off; off >>= 1) vs += __shfl_xor_sync(0xffffffffu, vs, off);
        float rstd = rsqrtf(vs * (1.f / 64.f) + 1e-6f);
        float y0 = d0 * rstd * sc[lane];
        float y1 = d1 * rstd * sc[lane + 32];
        p[lane]      = y0 * c - y1 * sn;
        p[lane + 32] = y1 * c + y0 * sn;
    }
}

// ======================= 4) flash attention, tf32 MMA ========================
// CTA = 128 q, 4 warps, warp = 32 q x 64 keys. Q in registers.
// K double-buffered + V prefetched via cp.async (raw f32, cvt at fragment load).
// Stride 72 (== 8 mod 32) -> all fragment patterns bank-conflict-free.
// Smem: K[2][64][72] + V[64][72] + P[128][72] = 90KB -> 2 CTAs/SM.
#define AST 72
#define SMEM_ATTN_BYTES (320 * AST * 4)

__device__ __forceinline__ void stage_async(float* dst, const float* src, int tid) {
    // 64x64 f32 tile: src stride 64, dst stride AST; 16B per cp.async
#pragma unroll
    for (int p = 0; p < 8; p++) {
        int idx = tid + p * 128;
        int r = idx >> 4, c = (idx & 15) * 4;
        uint32_t d = (uint32_t)__cvta_generic_to_shared(dst + r * AST + c);
        asm volatile("cp.async.cg.shared.global [%0], [%1], 16;"
                     :: "r"(d), "l"(src + r * 64 + c));
    }
}

__global__ __launch_bounds__(128) void attn_tc() {
    extern __shared__ float smf[];
    float* Kb0 = smf;
    float* Kb1 = smf + 64 * AST;
    float* Vb  = smf + 128 * AST;
    uint32_t* Pp = (uint32_t*)(smf + 192 * AST);

    int tid = threadIdx.x, lane = tid & 31, w = tid >> 5;
    int g = lane >> 2, tq = lane & 3;
    int bh = blockIdx.y, qt = blockIdx.x;                // 16 q-tiles of 128
    const float* kb = g_k + (size_t)bh * S_LEN * HD;
    const float* vb = g_v + (size_t)bh * S_LEN * HD;

    // ---- Q fragments in registers: 32 q rows per warp ----
    uint32_t qa[8][8];
#pragma unroll
    for (int i = 0; i < 2; i++) {
        const float* p0 = g_q + ((size_t)bh * S_LEN + qt * 128 + w * 32 + i * 16 + g) * HD;
        const float* p1 = p0 + 8 * HD;
#pragma unroll
        for (int ks = 0; ks < 8; ks++) {
            qa[ks][4 * i + 0] = f2tf(p0[8 * ks + tq]     * 0.125f);
            qa[ks][4 * i + 1] = f2tf(p1[8 * ks + tq]     * 0.125f);
            qa[ks][4 * i + 2] = f2tf(p0[8 * ks + tq + 4] * 0.125f);
            qa[ks][4 * i + 3] = f2tf(p1[8 * ks + tq + 4] * 0.125f);
        }
    }

    float o[2][8][4], mr[2][2], lr[2][2];
#pragma unroll
    for (int i = 0; i < 2; i++) {
        mr[i][0] = mr[i][1] = -1e30f;
        lr[i][0] = lr[i][1] = 0.f;
#pragma unroll
        for (int j = 0; j < 8; j++)
#pragma unroll
            for (int r = 0; r < 4; r++) o[i][j][r] = 0.f;
    }

    stage_async(Kb0, kb, tid);
    CP_COMMIT();

    for (int kt = 0; kt < S_LEN / 64; kt++) {
        CP_WAIT(0);            // K(kt) copies landed (this thread's)
        __syncthreads();       // K(kt) visible to all; V & other-K buffers free
        stage_async(Vb, vb + kt * 4096, tid);
        CP_COMMIT();
        int nt = (kt + 1 < S_LEN / 64) ? kt + 1 : kt;
        stage_async((kt & 1) ? Kb0 : Kb1, kb + nt * 4096, tid);
        CP_COMMIT();

        // ---- S = Q @ K^T ----
        const float* K = (kt & 1) ? Kb1 : Kb0;
        float s[2][8][4];
#pragma unroll
        for (int i = 0; i < 2; i++)
#pragma unroll
            for (int j = 0; j < 8; j++)
#pragma unroll
                for (int r = 0; r < 4; r++) s[i][j][r] = 0.f;
#pragma unroll
        for (int ks = 0; ks < 8; ks++) {
            int kk = ks * 8;
            uint32_t b[8][2];
#pragma unroll
            for (int j = 0; j < 8; j++) {
                int n = j * 8 + g;
                b[j][0] = f2tf(K[n * AST + kk + tq]);
                b[j][1] = f2tf(K[n * AST + kk + tq + 4]);
            }
#pragma unroll
            for (int i = 0; i < 2; i++)
#pragma unroll
                for (int j = 0; j < 8; j++)
                    mma_tf32(s[i][j], &qa[ks][4 * i], b[j], s[i][j]);
        }

        // ---- online softmax; write P (tf32) ----
#pragma unroll
        for (int i = 0; i < 2; i++) {
#pragma unroll
            for (int h = 0; h < 2; h++) {
                float rm = -1e30f;
#pragma unroll
                for (int j = 0; j < 8; j++)
                    rm = fmaxf(rm, fmaxf(s[i][j][2 * h], s[i][j][2 * h + 1]));
                rm = fmaxf(rm, __shfl_xor_sync(0xffffffffu, rm, 1));
                rm = fmaxf(rm, __shfl_xor_sync(0xffffffffu, rm, 2));
                float mn = fmaxf(mr[i][h], rm);
                float alpha = __expf(mr[i][h] - mn);
                mr[i][h] = mn;
                int row = w * 32 + i * 16 + h * 8 + g;
                float rs = 0.f;
#pragma unroll
                for (int j = 0; j < 8; j++) {
                    float p0 = __expf(s[i][j][2 * h] - mn);
                    float p1 = __expf(s[i][j][2 * h + 1] - mn);
                    rs += p0 + p1;
                    uint2 u; u.x = f2tf(p0); u.y = f2tf(p1);
                    *(uint2*)&Pp[row * AST + j * 8 + 2 * tq] = u;
                }
                rs += __shfl_xor_sync(0xffffffffu, rs, 1);
                rs += __shfl_xor_sync(0xffffffffu, rs, 2);
                lr[i][h] = lr[i][h] * alpha + rs;
#pragma unroll
                for (int j = 0; j < 8; j++) {
                    o[i][j][2 * h]     *= alpha;
                    o[i][j][2 * h + 1] *= alpha;
                }
            }
        }

        CP_WAIT(1);            // V(kt) done (K(kt+1) may still be in flight)
        __syncthreads();       // V visible to all

        // ---- O += P @ V ----
#pragma unroll
        for (int ks = 0; ks < 8; ks++) {
            int kk = ks * 8;
            uint32_t a[2][4], b[8][2];
#pragma unroll
            for (int i = 0; i < 2; i++) {
                int m = w * 32 + i * 16 + g;
                a[i][0] = Pp[m * AST + kk + tq];
                a[i][1] = Pp[(m + 8) * AST + kk + tq];
                a[i][2] = Pp[m * AST + kk + tq + 4];
                a[i][3] = Pp[(m + 8) * AST + kk + tq + 4];
            }
#pragma unroll
            for (int j = 0; j < 8; j++) {
                int n = j * 8 + g;
                b[j][0] = f2tf(Vb[(kk + tq) * AST + n]);
                b[j][1] = f2tf(Vb[(kk + tq + 4) * AST + n]);
            }
#pragma unroll
            for (int i = 0; i < 2; i++)
#pragma unroll
                for (int j = 0; j < 8; j++)
                    mma_tf32(o[i][j], a[i], b[j], o[i][j]);
        }
    }

    // ---- epilogue: divide by l, scatter token-major [b,s,h,hd] ----
    int b = bh >> 4, h4 = bh & 15;
#pragma unroll
    for (int i = 0; i < 2; i++) {
#pragma unroll
        for (int h = 0; h < 2; h++) {
            float invl = 1.f / lr[i][h];
            int srow = qt * 128 + w * 32 + i * 16 + h * 8 + g;
#pragma unroll
            for (int j = 0; j < 8; j++) {
                float2 f;
                f.x = o[i][j][2 * h]     * invl;
                f.y = o[i][j][2 * h + 1] * invl;
                int col = j * 8 + 2 * tq;
                *(float2*)(g_attn + (((size_t)b * S_LEN + srow) * NH + h4) * HD + col) = f;
            }
        }
    }
}

// =========================== launch ==========================================
extern "C" void kernel_launch(void* const* d_in, const int* in_sizes, int n_in,
                              void* d_out, int out_size) {
    const float* x        = (const float*)d_in[0];
    const float* w_qkv    = (const float*)d_in[1];
    const float* b_qkv    = (const float*)d_in[2];
    const float* w_out    = (const float*)d_in[3];
    const float* b_out    = (const float*)d_in[4];
    const float* ln_scale = (const float*)d_in[5];
    const float* ln_bias  = (const float*)d_in[6];
    const float* q_scale  = (const float*)d_in[7];
    const float* k_scale  = (const float*)d_in[8];
    float* out = (float*)d_out;

    cudaFuncSetAttribute(attn_tc, cudaFuncAttributeMaxDynamicSharedMemorySize,
                         SMEM_ATTN_BYTES);

    ln_kernel<<<NTOK, 256>>>(x, ln_scale, ln_bias);
    gemm_tc<<<dim3(3 * D_DIM / 128, NTOK / 128), 256>>>(w_qkv, b_qkv, nullptr, 0, 3 * D_DIM);
    lnrope_kernel<<<NB * NH * S_LEN / 8, 256>>>(q_scale, k_scale);
    attn_tc<<<dim3(S_LEN / 128, NB * NH), 128, SMEM_ATTN_BYTES>>>();
    gemm_tc<<<dim3(D_DIM / 128, NTOK / 128), 256>>>(w_out, b_out, out, 1, D_DIM);
}

// round 10
// speedup vs baseline: 1.3278x; 1.1955x over previous
#include <cuda_runtime.h>
#include <math.h>
#include <stdint.h>

// Problem constants
#define D_DIM 1024
#define S_LEN 2048
#define NB    2
#define NH    16
#define HD    64
#define NTOK  4096            // B*S
// -ln(10000)*2/64
#define NEG_LOG_BASE_OVER_32 (-0.28782313662425572f)

// ---------------- device scratch (allocation-free rule) ----------------------
__device__ float g_xn[NTOK * D_DIM];                 // layernorm(x), tf32-rounded
__device__ float g_q[NB * NH * S_LEN * HD];          // [b,h,s,hd], tf32-rounded
__device__ float g_k[NB * NH * S_LEN * HD];          // tf32-rounded
__device__ float g_v[NB * NH * S_LEN * HD];          // tf32-rounded
__device__ float g_attn[NTOK * D_DIM];               // [b,s,h,hd], tf32-rounded
__device__ float g_wq[D_DIM * 3 * D_DIM];            // tf32-rounded w_qkv
__device__ float g_wo[D_DIM * D_DIM];                // tf32-rounded w_out

// ---------------- tf32 helpers ----------------------------------------------
__device__ __forceinline__ uint32_t f2tf(float f) {
    uint32_t u;
    asm("cvt.rna.tf32.f32 %0, %1;" : "=r"(u) : "f"(f));
    return u;
}
__device__ __forceinline__ float roundtf(float f) { return __uint_as_float(f2tf(f)); }

// D = A(m16k8, row) * B(k8n8, col) + C, tf32 inputs, f32 accum
__device__ __forceinline__ void mma_tf32(float d[4], const uint32_t a[4],
                                         const uint32_t b[2], const float c[4]) {
    asm volatile(
        "mma.sync.aligned.m16n8k8.row.col.f32.tf32.tf32.f32 "
        "{%0,%1,%2,%3}, {%4,%5,%6,%7}, {%8,%9}, {%10,%11,%12,%13};"
        : "=f"(d[0]), "=f"(d[1]), "=f"(d[2]), "=f"(d[3])
        : "r"(a[0]), "r"(a[1]), "r"(a[2]), "r"(a[3]),
          "r"(b[0]), "r"(b[1]),
          "f"(c[0]), "f"(c[1]), "f"(c[2]), "f"(c[3]));
}

#define CP_COMMIT() asm volatile("cp.async.commit_group;" ::: "memory")
#define CP_WAIT(N)  asm volatile("cp.async.wait_group %0;" :: "n"(N) : "memory")

__device__ __forceinline__ void cp16(void* dst_smem, const float* src) {
    uint32_t d = (uint32_t)__cvta_generic_to_shared(dst_smem);
    asm volatile("cp.async.cg.shared.global [%0], [%1], 16;" :: "r"(d), "l"(src));
}

// ================= 0) round weights to tf32 once =============================
__global__ __launch_bounds__(256) void round_copy(const float* __restrict__ src,
                                                  float* __restrict__ dst) {
    int i = blockIdx.x * 256 + threadIdx.x;
    float4 f = ((const float4*)src)[i];
    float4 o;
    o.x = roundtf(f.x); o.y = roundtf(f.y); o.z = roundtf(f.z); o.w = roundtf(f.w);
    ((float4*)dst)[i] = o;
}

// ======================= 1) LayerNorm over D=1024 ============================
__global__ __launch_bounds__(256) void ln_kernel(const float* __restrict__ x,
                                                 const float* __restrict__ scale,
                                                 const float* __restrict__ bias) {
    int t = threadIdx.x;
    const float4* xr = (const float4*)(x + (size_t)blockIdx.x * D_DIM);
    float4 v = xr[t];
    float s  = v.x + v.y + v.z + v.w;
    float ss = v.x * v.x + v.y * v.y + v.z * v.z + v.w * v.w;
#pragma unroll
    for (int off = 16; off; off >>= 1) {
        s  += __shfl_xor_sync(0xffffffffu, s,  off);
        ss += __shfl_xor_sync(0xffffffffu, ss, off);
    }
    __shared__ float sm[8], sm2[8];
    int w = t >> 5;
    if ((t & 31) == 0) { sm[w] = s; sm2[w] = ss; }
    __syncthreads();
    if (t < 32) {
        float a = (t < 8) ? sm[t]  : 0.f;
        float b = (t < 8) ? sm2[t] : 0.f;
#pragma unroll
        for (int off = 4; off; off >>= 1) {
            a += __shfl_xor_sync(0xffffffffu, a, off);
            b += __shfl_xor_sync(0xffffffffu, b, off);
        }
        if (t == 0) { sm[0] = a; sm2[0] = b; }
    }
    __syncthreads();
    float mu   = sm[0]  * (1.f / 1024.f);
    float var  = sm2[0] * (1.f / 1024.f) - mu * mu;
    float rstd = rsqrtf(var + 1e-6f);
    float4 sc = ((const float4*)scale)[t];
    float4 bi = ((const float4*)bias)[t];
    float4 o;
    o.x = roundtf((v.x - mu) * rstd * sc.x + bi.x);
    o.y = roundtf((v.y - mu) * rstd * sc.y + bi.y);
    o.z = roundtf((v.z - mu) * rstd * sc.z + bi.z);
    o.w = roundtf((v.w - mu) * rstd * sc.w + bi.w);
    ((float4*)(g_xn + (size_t)blockIdx.x * D_DIM))[t] = o;
}

// ======================= 2)/5) tf32 GEMM, cp.async double-buffered ==========
// 128x128 tile, K-block 32, 8 warps (2x4), warp tile 64x32.
// As row-major [m][k] stride 36 (==4 mod 32); Bs [k][n] stride 136 (==8 mod 32).
// All operands pre-rounded in gmem -> zero cvts here.
#define AT 36
#define BT 136
#define GSTAGE (128 * AT + 32 * BT)                  // floats per stage
#define GEMM_SMEM_BYTES (2 * GSTAGE * 4)

__device__ __forceinline__ void stage_gemm(float* As, float* Bs,
                                           const float* __restrict__ A,
                                           const float* __restrict__ Bm,
                                           int row0, int col0, int k0, int N, int tid) {
#pragma unroll
    for (int p = 0; p < 4; p++) {                    // A: 128 x 32
        int idx = tid + p * 256;
        int r = idx >> 3, c = (idx & 7) * 4;
        cp16(As + r * AT + c, A + (size_t)(row0 + r) * 1024 + k0 + c);
    }
#pragma unroll
    for (int p = 0; p < 4; p++) {                    // B: 32 x 128
        int idx = tid + p * 256;
        int r = idx >> 5, c = (idx & 31) * 4;
        cp16(Bs + r * BT + c, Bm + (size_t)(k0 + r) * N + col0 + c);
    }
}

__global__ __launch_bounds__(256, 2) void gemm_tc(const float* __restrict__ Bmat,
                                                  const float* __restrict__ bias,
                                                  float* __restrict__ outC,
                                                  int mode, int N) {
    extern __shared__ float gs[];
    const float* A = mode ? g_attn : g_xn;
    int tid = threadIdx.x;
    int lane = tid & 31, warp = tid >> 5;
    int wm = warp >> 2, wn = warp & 3;
    int g = lane >> 2, tq = lane & 3;
    int row0 = blockIdx.y * 128, col0 = blockIdx.x * 128;

    float acc[4][4][4];
#pragma unroll
    for (int i = 0; i < 4; i++)
#pragma unroll
        for (int j = 0; j < 4; j++)
#pragma unroll
            for (int r = 0; r < 4; r++) acc[i][j][r] = 0.f;

    stage_gemm(gs, gs + 128 * AT, A, Bmat, row0, col0, 0, N, tid);
    CP_COMMIT();

    for (int kb = 0; kb < 32; kb++) {
        CP_WAIT(0);
        __syncthreads();
        if (kb + 1 < 32) {
            float* base = gs + ((kb + 1) & 1) * GSTAGE;
            stage_gemm(base, base + 128 * AT, A, Bmat, row0, col0, (kb + 1) * 32, N, tid);
            CP_COMMIT();
        }
        const uint32_t* As = (const uint32_t*)(gs + (kb & 1) * GSTAGE);
        const uint32_t* Bs = As + 128 * AT;
#pragma unroll
        for (int ks = 0; ks < 4; ks++) {
            int kk = ks * 8;
            uint32_t a[4][4], b[4][2];
#pragma unroll
            for (int i = 0; i < 4; i++) {
                int m = wm * 64 + i * 16 + g;
                a[i][0] = As[m * AT + kk + tq];
                a[i][1] = As[(m + 8) * AT + kk + tq];
                a[i][2] = As[m * AT + kk + tq + 4];
                a[i][3] = As[(m + 8) * AT + kk + tq + 4];
            }
#pragma unroll
            for (int j = 0; j < 4; j++) {
                int n = wn * 32 + j * 8 + g;
                b[j][0] = Bs[(kk + tq) * BT + n];
                b[j][1] = Bs[(kk + tq + 4) * BT + n];
            }
#pragma unroll
            for (int i = 0; i < 4; i++)
#pragma unroll
                for (int j = 0; j < 4; j++) mma_tf32(acc[i][j], a[i], b[j], acc[i][j]);
        }
        __syncthreads();
    }

#pragma unroll
    for (int i = 0; i < 4; i++) {
        int rbase = row0 + wm * 64 + i * 16 + g;
#pragma unroll
        for (int j = 0; j < 4; j++) {
            int cbase = col0 + wn * 32 + j * 8 + 2 * tq;
#pragma unroll
            for (int h = 0; h < 2; h++) {
                int row = rbase + 8 * h;
                float2 f;
                f.x = acc[i][j][2 * h + 0] + bias[cbase + 0];
                f.y = acc[i][j][2 * h + 1] + bias[cbase + 1];
                if (mode) {
                    *(float2*)(outC + (size_t)row * N + cbase) = f;
                } else {
                    int part = cbase >> 10;
                    float* dst = (part == 0) ? g_q : (part == 1) ? g_k : g_v;
                    if (part == 2) { f.x = roundtf(f.x); f.y = roundtf(f.y); }
                    int wd = cbase & 1023;
                    int head = wd >> 6, hd = wd & 63;
                    int b = row >> 11, s = row & 2047;
                    size_t di = ((((size_t)b * NH + head) * S_LEN) + s) * HD + hd;
                    *(float2*)(dst + di) = f;
                }
            }
        }
    }
}

// ================= 3) per-head LayerNorm + RoPE, tf32-rounded out ===========
__global__ __launch_bounds__(256) void lnrope_kernel(const float* __restrict__ q_scale,
                                                     const float* __restrict__ k_scale) {
    int gw   = (blockIdx.x * 256 + threadIdx.x) >> 5;   // (b*H+h)*S + s
    int lane = threadIdx.x & 31;
    int s = gw & 2047;

    float inv = expf((float)lane * NEG_LOG_BASE_OVER_32);
    float ang = (float)s * inv;
    float c, sn;
    sincosf(ang, &sn, &c);

#pragma unroll
    for (int sel = 0; sel < 2; sel++) {
        float* p = (sel ? g_k : g_q) + (size_t)gw * 64;
        const float* sc = sel ? k_scale : q_scale;
        float x0 = p[lane], x1 = p[lane + 32];
        float sum = x0 + x1;
#pragma unroll
        for (int off = 16; off; off >>= 1) sum += __shfl_xor_sync(0xffffffffu, sum, off);
        float mu = sum * (1.f / 64.f);
        float d0 = x0 - mu, d1 = x1 - mu;
        float vs = d0 * d0 + d1 * d1;
#pragma unroll
        for (int off = 16; off; off >>= 1) vs += __shfl_xor_sync(0xffffffffu, vs, off);
        float rstd = rsqrtf(vs * (1.f / 64.f) + 1e-6f);
        float y0 = d0 * rstd * sc[lane];
        float y1 = d1 * rstd * sc[lane + 32];
        p[lane]      = roundtf(y0 * c - y1 * sn);
        p[lane + 32] = roundtf(y1 * c + y0 * sn);
    }
}

// ======================= 4) flash attention, tf32 MMA ========================
// CTA = 128 q, 4 warps, warp = 32 q x 64 keys. Q in registers (pre-rounded).
// K double-buffered + V prefetched via cp.async; operands pre-rounded in gmem
// -> zero cvts in the mainloop. Stride 72 -> conflict-free fragments.
#define AST 72
#define SMEM_ATTN_BYTES (320 * AST * 4)

__device__ __forceinline__ void stage_async(float* dst, const float* src, int tid) {
#pragma unroll
    for (int p = 0; p < 8; p++) {
        int idx = tid + p * 128;
        int r = idx >> 4, c = (idx & 15) * 4;
        cp16(dst + r * AST + c, src + r * 64 + c);
    }
}

__global__ __launch_bounds__(128) void attn_tc() {
    extern __shared__ float smf[];
    float* Kb0 = smf;
    float* Kb1 = smf + 64 * AST;
    float* Vb  = smf + 128 * AST;
    uint32_t* Pp = (uint32_t*)(smf + 192 * AST);

    int tid = threadIdx.x, lane = tid & 31, w = tid >> 5;
    int g = lane >> 2, tq = lane & 3;
    int bh = blockIdx.y, qt = blockIdx.x;                // 16 q-tiles of 128
    const float* kb = g_k + (size_t)bh * S_LEN * HD;
    const float* vb = g_v + (size_t)bh * S_LEN * HD;

    // ---- Q fragments in registers: pre-rounded; *0.125 exact, no cvt ----
    uint32_t qa[8][8];
#pragma unroll
    for (int i = 0; i < 2; i++) {
        const float* p0 = g_q + ((size_t)bh * S_LEN + qt * 128 + w * 32 + i * 16 + g) * HD;
        const float* p1 = p0 + 8 * HD;
#pragma unroll
        for (int ks = 0; ks < 8; ks++) {
            qa[ks][4 * i + 0] = __float_as_uint(p0[8 * ks + tq]     * 0.125f);
            qa[ks][4 * i + 1] = __float_as_uint(p1[8 * ks + tq]     * 0.125f);
            qa[ks][4 * i + 2] = __float_as_uint(p0[8 * ks + tq + 4] * 0.125f);
            qa[ks][4 * i + 3] = __float_as_uint(p1[8 * ks + tq + 4] * 0.125f);
        }
    }

    float o[2][8][4], mr[2][2], lr[2][2];
#pragma unroll
    for (int i = 0; i < 2; i++) {
        mr[i][0] = mr[i][1] = -1e30f;
        lr[i][0] = lr[i][1] = 0.f;
#pragma unroll
        for (int j = 0; j < 8; j++)
#pragma unroll
            for (int r = 0; r < 4; r++) o[i][j][r] = 0.f;
    }

    stage_async(Kb0, kb, tid);
    CP_COMMIT();

    for (int kt = 0; kt < S_LEN / 64; kt++) {
        CP_WAIT(0);
        __syncthreads();
        stage_async(Vb, vb + kt * 4096, tid);
        CP_COMMIT();
        int nt = (kt + 1 < S_LEN / 64) ? kt + 1 : kt;
        stage_async((kt & 1) ? Kb0 : Kb1, kb + nt * 4096, tid);
        CP_COMMIT();

        // ---- S = Q @ K^T ----
        const uint32_t* K = (const uint32_t*)((kt & 1) ? Kb1 : Kb0);
        float s[2][8][4];
#pragma unroll
        for (int i = 0; i < 2; i++)
#pragma unroll
            for (int j = 0; j < 8; j++)
#pragma unroll
                for (int r = 0; r < 4; r++) s[i][j][r] = 0.f;
#pragma unroll
        for (int ks = 0; ks < 8; ks++) {
            int kk = ks * 8;
            uint32_t b[8][2];
#pragma unroll
            for (int j = 0; j < 8; j++) {
                int n = j * 8 + g;
                b[j][0] = K[n * AST + kk + tq];
                b[j][1] = K[n * AST + kk + tq + 4];
            }
#pragma unroll
            for (int i = 0; i < 2; i++)
#pragma unroll
                for (int j = 0; j < 8; j++)
                    mma_tf32(s[i][j], &qa[ks][4 * i], b[j], s[i][j]);
        }

        // ---- online softmax; write P (tf32) ----
#pragma unroll
        for (int i = 0; i < 2; i++) {
#pragma unroll
            for (int h = 0; h < 2; h++) {
                float rm = -1e30f;
#pragma unroll
                for (int j = 0; j < 8; j++)
                    rm = fmaxf(rm, fmaxf(s[i][j][2 * h], s[i][j][2 * h + 1]));
                rm = fmaxf(rm, __shfl_xor_sync(0xffffffffu, rm, 1));
                rm = fmaxf(rm, __shfl_xor_sync(0xffffffffu, rm, 2));
                float mn = fmaxf(mr[i][h], rm);
                float alpha = __expf(mr[i][h] - mn);
                mr[i][h] = mn;
                int row = w * 32 + i * 16 + h * 8 + g;
                float rs = 0.f;
#pragma unroll
                for (int j = 0; j < 8; j++) {
                    float p0 = __expf(s[i][j][2 * h] - mn);
                    float p1 = __expf(s[i][j][2 * h + 1] - mn);
                    rs += p0 + p1;
                    uint2 u; u.x = f2tf(p0); u.y = f2tf(p1);
                    *(uint2*)&Pp[row * AST + j * 8 + 2 * tq] = u;
                }
                rs += __shfl_xor_sync(0xffffffffu, rs, 1);
                rs += __shfl_xor_sync(0xffffffffu, rs, 2);
                lr[i][h] = lr[i][h] * alpha + rs;
#pragma unroll
                for (int j = 0; j < 8; j++) {
                    o[i][j][2 * h]     *= alpha;
                    o[i][j][2 * h + 1] *= alpha;
                }
            }
        }

        CP_WAIT(1);            // V(kt) done (K(kt+1) may still be in flight)
        __syncthreads();

        // ---- O += P @ V ----
        const uint32_t* V = (const uint32_t*)Vb;
#pragma unroll
        for (int ks = 0; ks < 8; ks++) {
            int kk = ks * 8;
            uint32_t a[2][4], b[8][2];
#pragma unroll
            for (int i = 0; i < 2; i++) {
                int m = w * 32 + i * 16 + g;
                a[i][0] = Pp[m * AST + kk + tq];
                a[i][1] = Pp[(m + 8) * AST + kk + tq];
                a[i][2] = Pp[m * AST + kk + tq + 4];
                a[i][3] = Pp[(m + 8) * AST + kk + tq + 4];
            }
#pragma unroll
            for (int j = 0; j < 8; j++) {
                int n = j * 8 + g;
                b[j][0] = V[(kk + tq) * AST + n];
                b[j][1] = V[(kk + tq + 4) * AST + n];
            }
#pragma unroll
            for (int i = 0; i < 2; i++)
#pragma unroll
                for (int j = 0; j < 8; j++)
                    mma_tf32(o[i][j], a[i], b[j], o[i][j]);
        }
    }

    // ---- epilogue: divide by l, round to tf32, scatter [b,s,h,hd] ----
    int b = bh >> 4, h4 = bh & 15;
#pragma unroll
    for (int i = 0; i < 2; i++) {
#pragma unroll
        for (int h = 0; h < 2; h++) {
            float invl = 1.f / lr[i][h];
            int srow = qt * 128 + w * 32 + i * 16 + h * 8 + g;
#pragma unroll
            for (int j = 0; j < 8; j++) {
                float2 f;
                f.x = roundtf(o[i][j][2 * h]     * invl);
                f.y = roundtf(o[i][j][2 * h + 1] * invl);
                int col = j * 8 + 2 * tq;
                *(float2*)(g_attn + (((size_t)b * S_LEN + srow) * NH + h4) * HD + col) = f;
            }
        }
    }
}

// =========================== launch ==========================================
extern "C" void kernel_launch(void* const* d_in, const int* in_sizes, int n_in,
                              void* d_out, int out_size) {
    const float* x        = (const float*)d_in[0];
    const float* w_qkv    = (const float*)d_in[1];
    const float* b_qkv    = (const float*)d_in[2];
    const float* w_out    = (const float*)d_in[3];
    const float* b_out    = (const float*)d_in[4];
    const float* ln_scale = (const float*)d_in[5];
    const float* ln_bias  = (const float*)d_in[6];
    const float* q_scale  = (const float*)d_in[7];
    const float* k_scale  = (const float*)d_in[8];
    float* out = (float*)d_out;

    cudaFuncSetAttribute(attn_tc, cudaFuncAttributeMaxDynamicSharedMemorySize,
                         SMEM_ATTN_BYTES);
    cudaFuncSetAttribute(gemm_tc, cudaFuncAttributeMaxDynamicSharedMemorySize,
                         GEMM_SMEM_BYTES);

    float* wq;  cudaGetSymbolAddress((void**)&wq, g_wq);
    float* wo;  cudaGetSymbolAddress((void**)&wo, g_wo);

    round_copy<<<(D_DIM * 3 * D_DIM / 4) / 256, 256>>>(w_qkv, wq);
    round_copy<<<(D_DIM * D_DIM / 4) / 256, 256>>>(w_out, wo);
    ln_kernel<<<NTOK, 256>>>(x, ln_scale, ln_bias);
    gemm_tc<<<dim3(3 * D_DIM / 128, NTOK / 128), 256, GEMM_SMEM_BYTES>>>(wq, b_qkv, nullptr, 0, 3 * D_DIM);
    lnrope_kernel<<<NB * NH * S_LEN / 8, 256>>>(q_scale, k_scale);
    attn_tc<<<dim3(S_LEN / 128, NB * NH), 128, SMEM_ATTN_BYTES>>>();
    gemm_tc<<<dim3(D_DIM / 128, NTOK / 128), 256, GEMM_SMEM_BYTES>>>(wo, b_out, out, 1, D_DIM);
}